// round 14
// baseline (speedup 1.0000x reference)
#include <cuda_runtime.h>
#include <cuda_fp16.h>
#include <cstdint>
#include <cstddef>

#define Bb 2
#define Ss 2048
#define Ee 1024
#define Hh 16
#define Dd 64
#define Mm (Bb*Ss)

// ---------------------------------------------------------------------------
// Scratch (fp16 operand chain + fp32 v for residual)
// ---------------------------------------------------------------------------
__device__ __half g_xh [Mm * Ee];     // x in fp16
__device__ __half g_wqh[Ee * Ee];
__device__ __half g_wkh[Ee * Ee];
__device__ __half g_wvh[Ee * Ee];
__device__ __half g_woh[Ee * Ee];
__device__ __half g_qh [Mm * Ee];     // q (fp16)
__device__ __half g_kh [Mm * Ee];     // k (fp16)
__device__ __half g_avh[Mm * Ee];     // g ⊙ v (fp16)
__device__ float  g_v  [Mm * Ee];     // v (fp32, residual)

// ---------------------------------------------------------------------------
// Helpers (family-agnostic PTX: cp.async, ldmatrix, mma.sync — sm_80+)
// ---------------------------------------------------------------------------
__device__ __forceinline__ uint32_t smem_u32(const void* p) {
    uint32_t a;
    asm("{ .reg .u64 t; cvta.to.shared.u64 t, %1; cvt.u32.u64 %0, t; }"
        : "=r"(a) : "l"(p));
    return a;
}
__device__ __forceinline__ void cpa16(uint32_t s, const void* g) {
    asm volatile("cp.async.cg.shared.global [%0], [%1], 16;" :: "r"(s), "l"(g));
}
__device__ __forceinline__ void cpa_commit() {
    asm volatile("cp.async.commit_group;" ::: "memory");
}
template<int N> __device__ __forceinline__ void cpa_wait() {
    asm volatile("cp.async.wait_group %0;" :: "n"(N) : "memory");
}
__device__ __forceinline__ void ldsm4(uint32_t& r0, uint32_t& r1,
                                      uint32_t& r2, uint32_t& r3, uint32_t addr) {
    asm volatile("ldmatrix.sync.aligned.m8n8.x4.shared.b16 {%0,%1,%2,%3}, [%4];"
                 : "=r"(r0), "=r"(r1), "=r"(r2), "=r"(r3) : "r"(addr));
}
// f16 mma, fp32 accumulate
__device__ __forceinline__ void mma16(float* c, const uint32_t* a,
                                      uint32_t b0, uint32_t b1) {
    asm volatile(
        "mma.sync.aligned.m16n8k16.row.col.f32.f16.f16.f32 "
        "{%0,%1,%2,%3}, {%4,%5,%6,%7}, {%8,%9}, {%0,%1,%2,%3};"
        : "+f"(c[0]), "+f"(c[1]), "+f"(c[2]), "+f"(c[3])
        : "r"(a[0]), "r"(a[1]), "r"(a[2]), "r"(a[3]), "r"(b0), "r"(b1));
}

// FFMA-only exp
__device__ __forceinline__ float fast_exp(float x) {
    float t = x * 1.4426950408889634f;
    int   e = __float2int_rn(t);
    float f = t - (float)e;
    float p = 0.0013333558146428443f;
    p = fmaf(p, f, 0.009618129842126066f);
    p = fmaf(p, f, 0.05550410866482158f);
    p = fmaf(p, f, 0.2402265069591007f);
    p = fmaf(p, f, 0.6931471805599453f);
    p = fmaf(p, f, 1.0f);
    return p * __int_as_float((e + 127) << 23);
}

// ---------------------------------------------------------------------------
// fp32 -> fp16 (RN) pre-pass: one launch converts x + all 4 weights
// ---------------------------------------------------------------------------
__global__ void __launch_bounds__(256) cvt_all(const float* __restrict__ x,
                                               const float* __restrict__ wq,
                                               const float* __restrict__ wk,
                                               const float* __restrict__ wv,
                                               const float* __restrict__ wo)
{
    long i = ((long)blockIdx.x * 256 + threadIdx.x) * 4;
    const float* src; __half* dst; long off;
    if (i < (long)Mm * Ee) {
        src = x; dst = g_xh; off = i;
    } else {
        long j = i - (long)Mm * Ee;
        int  w = (int)(j >> 20);                 // Ee*Ee = 1<<20
        off = j & ((1L << 20) - 1);
        src = (w == 0) ? wq : (w == 1) ? wk : (w == 2) ? wv : wo;
        dst = (w == 0) ? g_wqh : (w == 1) ? g_wkh : (w == 2) ? g_wvh : g_woh;
    }
    float4 v = *(const float4*)&src[off];
    *(__half2*)&dst[off]     = __floats2half2_rn(v.x, v.y);
    *(__half2*)&dst[off + 2] = __floats2half2_rn(v.z, v.w);
}

// ---------------------------------------------------------------------------
// fp16 GEMM core: C[128x128] = A[128xK] @ Bw[128xK]^T (+Resid)
// 256 threads (8 warps, 2x4). Warp tile 64x32. BK=64 halves, 3-stage cp.async.
// ---------------------------------------------------------------------------
template<bool HALF_OUT, bool RES>
__device__ __forceinline__ void gemm_core(const __half* __restrict__ A,
                                          const __half* __restrict__ Bw,
                                          __half* __restrict__ Ch,
                                          float* __restrict__ Cf,
                                          const float* __restrict__ Resid,
                                          int m0, int n0, char* dsm)
{
    const uint32_t stg = smem_u32(dsm);
    const int tid = threadIdx.x;
    const int wid = tid >> 5, lane = tid & 31;
    const int wr = wid >> 2, wc = wid & 3;

    auto load_stage = [&](int kb) {
        uint32_t s = stg + (uint32_t)(kb % 3) * 32768u;
        int k0 = kb * 64;                  // in halves
#pragma unroll
        for (int i = 0; i < 8; i++) {
            int j     = tid + i * 256;     // 0..2047
            int which = j >> 10;           // 0:A 1:B
            int idx   = j & 1023;
            int r     = idx >> 3;          // 0..127
            int ch    = idx & 7;           // 16B chunk (8 halves)
            uint32_t dst = s + (uint32_t)which * 16384u
                         + (uint32_t)r * 128u + ((uint32_t)(ch ^ (r & 7)) << 4);
            const __half* src = which ? &Bw[(size_t)(n0 + r) * Ee + k0 + ch * 8]
                                      : &A [(size_t)(m0 + r) * Ee + k0 + ch * 8];
            cpa16(dst, src);
        }
        cpa_commit();
    };

    float acc[4][4][4];
#pragma unroll
    for (int i = 0; i < 4; i++)
#pragma unroll
        for (int j = 0; j < 4; j++)
#pragma unroll
            for (int k = 0; k < 4; k++) acc[i][j][k] = 0.f;

    load_stage(0); load_stage(1);

    const int rA = wr * 64 + (lane & 15);
    const int cAadd = lane >> 4;
    const int rB = wc * 32 + (lane & 7) + ((lane >> 4) << 3);
    const int cBadd = (lane >> 3) & 1;

    for (int kb = 0; kb < 16; ++kb) {
        if (kb + 2 < 16) cpa_wait<1>(); else cpa_wait<0>();
        __syncthreads();
        if (kb + 2 < 16) load_stage(kb + 2);

        uint32_t As = stg + (uint32_t)(kb % 3) * 32768u;
        uint32_t Bs = As + 16384u;
#pragma unroll
        for (int ks = 0; ks < 4; ++ks) {            // 4 x k16
            uint32_t a[4][4];
#pragma unroll
            for (int mi = 0; mi < 4; mi++) {
                int row = rA + mi * 16;
                int ch  = 2 * ks + cAadd;
                uint32_t addr = As + (uint32_t)row * 128u
                              + ((uint32_t)(ch ^ (row & 7)) << 4);
                ldsm4(a[mi][0], a[mi][1], a[mi][2], a[mi][3], addr);
            }
            uint32_t b[2][4];
#pragma unroll
            for (int njp = 0; njp < 2; njp++) {
                int row = rB + njp * 16;
                int ch  = 2 * ks + cBadd;
                uint32_t addr = Bs + (uint32_t)row * 128u
                              + ((uint32_t)(ch ^ (row & 7)) << 4);
                ldsm4(b[njp][0], b[njp][1], b[njp][2], b[njp][3], addr);
            }
#pragma unroll
            for (int mi = 0; mi < 4; mi++)
#pragma unroll
                for (int nj = 0; nj < 4; nj++)
                    mma16(acc[mi][nj], a[mi],
                          b[nj >> 1][(nj & 1) * 2], b[nj >> 1][(nj & 1) * 2 + 1]);
        }
    }

#pragma unroll
    for (int mi = 0; mi < 4; mi++) {
        int r0 = m0 + wr * 64 + mi * 16 + (lane >> 2);
#pragma unroll
        for (int nj = 0; nj < 4; nj++) {
            int c0 = n0 + wc * 32 + nj * 8 + 2 * (lane & 3);
            if (HALF_OUT) {
                *(__half2*)&Ch[(size_t)r0 * Ee + c0] =
                    __floats2half2_rn(acc[mi][nj][0], acc[mi][nj][1]);
                *(__half2*)&Ch[(size_t)(r0 + 8) * Ee + c0] =
                    __floats2half2_rn(acc[mi][nj][2], acc[mi][nj][3]);
            } else {
                float2 v0 = {acc[mi][nj][0], acc[mi][nj][1]};
                float2 v1 = {acc[mi][nj][2], acc[mi][nj][3]};
                if (RES) {
                    float2 a0 = *(const float2*)&Resid[(size_t)r0 * Ee + c0];
                    float2 a1 = *(const float2*)&Resid[(size_t)(r0 + 8) * Ee + c0];
                    v0.x += a0.x; v0.y += a0.y; v1.x += a1.x; v1.y += a1.y;
                }
                *(float2*)&Cf[(size_t)r0 * Ee + c0]       = v0;
                *(float2*)&Cf[(size_t)(r0 + 8) * Ee + c0] = v1;
            }
        }
    }
}

// per-batch qkv: grid (8, 16, 3); m rows of batch bsel only
__global__ void __launch_bounds__(256, 2)
tc_qkv(int bsel)
{
    extern __shared__ char dsm[];
    int z = blockIdx.z;
    const __half* W = (z == 0) ? g_wqh : (z == 1) ? g_wkh : g_wvh;
    int m0 = bsel * Ss + blockIdx.y * 128;
    if (z == 2)
        gemm_core<false, false>(g_xh, W, nullptr, g_v, nullptr,
                                m0, blockIdx.x * 128, dsm);
    else
        gemm_core<true, false>(g_xh, W, (z == 0) ? g_qh : g_kh, nullptr, nullptr,
                               m0, blockIdx.x * 128, dsm);
}

// per-batch out: grid (8, 16)
__global__ void __launch_bounds__(256, 2)
tc_out(float* __restrict__ Out, int bsel)
{
    extern __shared__ char dsm[];
    gemm_core<false, true>(g_avh, g_woh, nullptr, Out, g_v,
                           bsel * Ss + blockIdx.y * 128, blockIdx.x * 128, dsm);
}

// ---------------------------------------------------------------------------
// Score pass (fp16 q,k), per batch: grid (16 qtiles LPT, 16 heads).
// S = Q[128x64] @ K[128x64]^T per causal k-tile, exp + row sums in regs,
// fused epilogue writes g_avh = (diag/rowsum) * v for this head slice.
// 256 threads, 8 warps (2x4), warp tile 64x32. SMEM: Q 16KB + 3 K x 16KB.
// ---------------------------------------------------------------------------
__global__ void __launch_bounds__(256, 2)
tc_score(int bsel)
{
    extern __shared__ char dsm[];
    const uint32_t Qs = smem_u32(dsm);
    const uint32_t Ks = Qs + 16384u;
    float* sSum  = (float*)(dsm + 16384 + 3 * 16384);
    float* sDiag = sSum + 128;

    const int qt = (int)(gridDim.x - 1 - blockIdx.x);   // LPT: heavy first
    const int h = blockIdx.y, b = bsel;
    const int tid = threadIdx.x;
    const int wid = tid >> 5, lane = tid & 31;
    const int wr = wid >> 2, wc = wid & 3;

    auto load_q = [&]() {
#pragma unroll
        for (int i = 0; i < 4; i++) {
            int j  = tid + i * 256;     // 0..1023
            int r  = j >> 3;            // 0..127
            int ch = j & 7;             // 8 chunks (64 halves/row)
            uint32_t dst = Qs + (uint32_t)r * 128u + ((uint32_t)(ch ^ (r & 7)) << 4);
            cpa16(dst, &g_qh[(size_t)(b * Ss + qt * 128 + r) * Ee + h * Dd + ch * 8]);
        }
    };
    auto load_k = [&](int kt, int slot) {
        uint32_t s = Ks + (uint32_t)slot * 16384u;
#pragma unroll
        for (int i = 0; i < 4; i++) {
            int j  = tid + i * 256;
            int r  = j >> 3;
            int ch = j & 7;
            uint32_t dst = s + (uint32_t)r * 128u + ((uint32_t)(ch ^ (r & 7)) << 4);
            cpa16(dst, &g_kh[(size_t)(b * Ss + kt * 128 + r) * Ee + h * Dd + ch * 8]);
        }
    };

    load_q(); load_k(0, 0); cpa_commit();
    if (qt >= 1) { load_k(1, 1); cpa_commit(); }

    if (tid < 128) { sSum[tid] = 0.f; sDiag[tid] = 0.f; }

    float rs[8], dv[8];
#pragma unroll
    for (int k = 0; k < 8; k++) { rs[k] = 0.f; dv[k] = 0.f; }

    const int rA = wr * 64 + (lane & 15);
    const int cAadd = lane >> 4;
    const int rB = wc * 32 + (lane & 7) + ((lane >> 4) << 3);
    const int cBadd = (lane >> 3) & 1;

    for (int kt = 0; kt <= qt; ++kt) {
        if (kt == qt) cpa_wait<0>(); else cpa_wait<1>();
        __syncthreads();
        if (kt + 2 <= qt) { load_k(kt + 2, (kt + 2) % 3); cpa_commit(); }

        float acc[4][4][4];
#pragma unroll
        for (int i = 0; i < 4; i++)
#pragma unroll
            for (int j = 0; j < 4; j++)
#pragma unroll
                for (int k = 0; k < 4; k++) acc[i][j][k] = 0.f;

        uint32_t Ksl = Ks + (uint32_t)(kt % 3) * 16384u;
#pragma unroll
        for (int ks = 0; ks < 4; ++ks) {
            uint32_t a[4][4];
#pragma unroll
            for (int mi = 0; mi < 4; mi++) {
                int row = rA + mi * 16;
                int ch  = 2 * ks + cAadd;
                uint32_t addr = Qs + (uint32_t)row * 128u
                              + ((uint32_t)(ch ^ (row & 7)) << 4);
                ldsm4(a[mi][0], a[mi][1], a[mi][2], a[mi][3], addr);
            }
            uint32_t bfr[2][4];
#pragma unroll
            for (int njp = 0; njp < 2; njp++) {
                int row = rB + njp * 16;
                int ch  = 2 * ks + cBadd;
                uint32_t addr = Ksl + (uint32_t)row * 128u
                              + ((uint32_t)(ch ^ (row & 7)) << 4);
                ldsm4(bfr[njp][0], bfr[njp][1], bfr[njp][2], bfr[njp][3], addr);
            }
#pragma unroll
            for (int mi = 0; mi < 4; mi++)
#pragma unroll
                for (int nj = 0; nj < 4; nj++)
                    mma16(acc[mi][nj], a[mi],
                          bfr[nj >> 1][(nj & 1) * 2], bfr[nj >> 1][(nj & 1) * 2 + 1]);
        }

        const bool dt = (kt == qt);
#pragma unroll
        for (int mi = 0; mi < 4; mi++) {
            int il0 = wr * 64 + mi * 16 + (lane >> 2);
#pragma unroll
            for (int nj = 0; nj < 4; nj++) {
                int jl = wc * 32 + nj * 8 + 2 * (lane & 3);
#pragma unroll
                for (int q = 0; q < 4; q++) {
                    int il = il0 + (q >> 1) * 8;
                    int j  = jl  + (q & 1);
                    float e = fast_exp(acc[mi][nj][q] * 0.03125f);
                    if (dt) {
                        if (j > il)  e = 0.f;
                        if (j == il) dv[mi * 2 + (q >> 1)] = e;
                    }
                    rs[mi * 2 + (q >> 1)] += e;
                }
            }
        }
    }

    // quad reduce (lanes in a quad share rows), then cross-warp via smem atomics
#pragma unroll
    for (int k = 0; k < 8; k++) {
        rs[k] += __shfl_xor_sync(0xffffffffu, rs[k], 1);
        rs[k] += __shfl_xor_sync(0xffffffffu, rs[k], 2);
        dv[k] += __shfl_xor_sync(0xffffffffu, dv[k], 1);
        dv[k] += __shfl_xor_sync(0xffffffffu, dv[k], 2);
    }
    if ((lane & 3) == 0) {
#pragma unroll
        for (int k = 0; k < 8; k++) {
            int row = wr * 64 + (k >> 1) * 16 + (k & 1) * 8 + (lane >> 2);
            atomicAdd(&sSum[row], rs[k]);
            atomicAdd(&sDiag[row], dv[k]);
        }
    }
    __syncthreads();

    // fused gv epilogue: g_avh[row, head slice] = (diag/rowsum) * v
    {
        int r  = tid >> 1;                   // 0..127
        int c0 = (tid & 1) * 32;             // half of the 64-wide head slice
        float gv = sDiag[r] / sSum[r];
        size_t rowg = (size_t)(b * Ss + qt * 128 + r) * Ee + h * Dd + c0;
#pragma unroll
        for (int c = 0; c < 32; c += 4) {
            float4 v = *(const float4*)&g_v[rowg + c];
            *(__half2*)&g_avh[rowg + c]     = __floats2half2_rn(v.x * gv, v.y * gv);
            *(__half2*)&g_avh[rowg + c + 2] = __floats2half2_rn(v.z * gv, v.w * gv);
        }
    }
}

// ---------------------------------------------------------------------------
extern "C" void kernel_launch(void* const* d_in, const int* in_sizes, int n_in,
                              void* d_out, int out_size)
{
    const float* x  = (const float*)d_in[0];
    const float* wq = (const float*)d_in[1];
    const float* wk = (const float*)d_in[2];
    const float* wv = (const float*)d_in[3];
    const float* wo = (const float*)d_in[4];
    float* out = (float*)d_out;

    const int SMEM_GEMM  = 3 * 32768;                 // 96 KB
    const int SMEM_SCORE = 16384 + 3 * 16384 + 1024;  // 64 KB + reduce

    cudaFuncSetAttribute(tc_qkv,   cudaFuncAttributeMaxDynamicSharedMemorySize, SMEM_GEMM);
    cudaFuncSetAttribute(tc_out,   cudaFuncAttributeMaxDynamicSharedMemorySize, SMEM_GEMM);
    cudaFuncSetAttribute(tc_score, cudaFuncAttributeMaxDynamicSharedMemorySize, SMEM_SCORE);

    // one fused fp32->fp16 RN conversion launch (x + 4 weights)
    const long TOT = (long)Mm * Ee + 4L * Ee * Ee;    // 8388608
    cvt_all<<<(unsigned)(TOT / 4 / 256), 256>>>(x, wq, wk, wv, wo);

    // Fork two independent per-batch chains so their waves interleave.
    cudaStream_t sB;
    cudaStreamCreateWithFlags(&sB, cudaStreamNonBlocking);
    cudaEvent_t evF, evB;
    cudaEventCreateWithFlags(&evF, cudaEventDisableTiming);
    cudaEventCreateWithFlags(&evB, cudaEventDisableTiming);

    cudaEventRecord(evF, 0);
    cudaStreamWaitEvent(sB, evF, 0);

    // chain A (batch 0) on the default stream
    tc_qkv  <<<dim3(8, 16, 3), 256, SMEM_GEMM,  0>>>(0);
    tc_score<<<dim3(16, 16),   256, SMEM_SCORE, 0>>>(0);
    tc_out  <<<dim3(8, 16),    256, SMEM_GEMM,  0>>>(out, 0);

    // chain B (batch 1) on sB
    tc_qkv  <<<dim3(8, 16, 3), 256, SMEM_GEMM,  sB>>>(1);
    tc_score<<<dim3(16, 16),   256, SMEM_SCORE, sB>>>(1);
    tc_out  <<<dim3(8, 16),    256, SMEM_GEMM,  sB>>>(out, 1);

    cudaEventRecord(evB, sB);
    cudaStreamWaitEvent(0, evB, 0);
}

// round 16
// speedup vs baseline: 1.0137x; 1.0137x over previous
#include <cuda_runtime.h>
#include <cuda_fp16.h>
#include <cstdint>
#include <cstddef>

#define Bb 2
#define Ss 2048
#define Ee 1024
#define Hh 16
#define Dd 64
#define Mm (Bb*Ss)

// ---------------------------------------------------------------------------
// Scratch (fp16 operand chain + fp32 v for residual)
// ---------------------------------------------------------------------------
__device__ __half g_xh [Mm * Ee];     // x in fp16
__device__ __half g_wqh[Ee * Ee];
__device__ __half g_wkh[Ee * Ee];
__device__ __half g_wvh[Ee * Ee];
__device__ __half g_woh[Ee * Ee];
__device__ __half g_qh [Mm * Ee];     // q (fp16)
__device__ __half g_kh [Mm * Ee];     // k (fp16)
__device__ __half g_avh[Mm * Ee];     // g ⊙ v (fp16)
__device__ float  g_v  [Mm * Ee];     // v (fp32, residual)

// ---------------------------------------------------------------------------
// Helpers (family-agnostic PTX: cp.async, ldmatrix, mma.sync — sm_80+)
// ---------------------------------------------------------------------------
__device__ __forceinline__ uint32_t smem_u32(const void* p) {
    uint32_t a;
    asm("{ .reg .u64 t; cvta.to.shared.u64 t, %1; cvt.u32.u64 %0, t; }"
        : "=r"(a) : "l"(p));
    return a;
}
__device__ __forceinline__ void cpa16(uint32_t s, const void* g) {
    asm volatile("cp.async.cg.shared.global [%0], [%1], 16;" :: "r"(s), "l"(g));
}
__device__ __forceinline__ void cpa_commit() {
    asm volatile("cp.async.commit_group;" ::: "memory");
}
template<int N> __device__ __forceinline__ void cpa_wait() {
    asm volatile("cp.async.wait_group %0;" :: "n"(N) : "memory");
}
__device__ __forceinline__ void ldsm4(uint32_t& r0, uint32_t& r1,
                                      uint32_t& r2, uint32_t& r3, uint32_t addr) {
    asm volatile("ldmatrix.sync.aligned.m8n8.x4.shared.b16 {%0,%1,%2,%3}, [%4];"
                 : "=r"(r0), "=r"(r1), "=r"(r2), "=r"(r3) : "r"(addr));
}
// f16 mma, fp32 accumulate
__device__ __forceinline__ void mma16(float* c, const uint32_t* a,
                                      uint32_t b0, uint32_t b1) {
    asm volatile(
        "mma.sync.aligned.m16n8k16.row.col.f32.f16.f16.f32 "
        "{%0,%1,%2,%3}, {%4,%5,%6,%7}, {%8,%9}, {%0,%1,%2,%3};"
        : "+f"(c[0]), "+f"(c[1]), "+f"(c[2]), "+f"(c[3])
        : "r"(a[0]), "r"(a[1]), "r"(a[2]), "r"(a[3]), "r"(b0), "r"(b1));
}

// FFMA-only exp
__device__ __forceinline__ float fast_exp(float x) {
    float t = x * 1.4426950408889634f;
    int   e = __float2int_rn(t);
    float f = t - (float)e;
    float p = 0.0013333558146428443f;
    p = fmaf(p, f, 0.009618129842126066f);
    p = fmaf(p, f, 0.05550410866482158f);
    p = fmaf(p, f, 0.2402265069591007f);
    p = fmaf(p, f, 0.6931471805599453f);
    p = fmaf(p, f, 1.0f);
    return p * __int_as_float((e + 127) << 23);
}

__device__ __forceinline__ uint32_t pack_h2(float a, float b) {
    __half2 h = __floats2half2_rn(a, b);
    return *(uint32_t*)&h;
}

// ---------------------------------------------------------------------------
// fp32 -> fp16 (RN) pre-passes: x on one stream, weights on the other
// ---------------------------------------------------------------------------
__global__ void __launch_bounds__(256) cvt_x(const float* __restrict__ x)
{
    long i = ((long)blockIdx.x * 256 + threadIdx.x) * 4;
    float4 v = *(const float4*)&x[i];
    *(__half2*)&g_xh[i]     = __floats2half2_rn(v.x, v.y);
    *(__half2*)&g_xh[i + 2] = __floats2half2_rn(v.z, v.w);
}

__global__ void __launch_bounds__(256) cvt_w(const float* __restrict__ wq,
                                             const float* __restrict__ wk,
                                             const float* __restrict__ wv,
                                             const float* __restrict__ wo)
{
    long j = ((long)blockIdx.x * 256 + threadIdx.x) * 4;
    int  w = (int)(j >> 20);                 // Ee*Ee = 1<<20
    long off = j & ((1L << 20) - 1);
    const float* src = (w == 0) ? wq : (w == 1) ? wk : (w == 2) ? wv : wo;
    __half* dst = (w == 0) ? g_wqh : (w == 1) ? g_wkh : (w == 2) ? g_wvh : g_woh;
    float4 v = *(const float4*)&src[off];
    *(__half2*)&dst[off]     = __floats2half2_rn(v.x, v.y);
    *(__half2*)&dst[off + 2] = __floats2half2_rn(v.z, v.w);
}

// ---------------------------------------------------------------------------
// fp16 GEMM core: C[128x128] = A[128xK] @ Bw[128xK]^T (+Resid)
// 256 threads (8 warps, 2x4). Warp tile 64x32. BK=64 halves, 3-stage cp.async.
// ---------------------------------------------------------------------------
template<bool HALF_OUT, bool RES>
__device__ __forceinline__ void gemm_core(const __half* __restrict__ A,
                                          const __half* __restrict__ Bw,
                                          __half* __restrict__ Ch,
                                          float* __restrict__ Cf,
                                          const float* __restrict__ Resid,
                                          int m0, int n0, char* dsm)
{
    const uint32_t stg = smem_u32(dsm);
    const int tid = threadIdx.x;
    const int wid = tid >> 5, lane = tid & 31;
    const int wr = wid >> 2, wc = wid & 3;

    auto load_stage = [&](int kb) {
        uint32_t s = stg + (uint32_t)(kb % 3) * 32768u;
        int k0 = kb * 64;                  // in halves
#pragma unroll
        for (int i = 0; i < 8; i++) {
            int j     = tid + i * 256;     // 0..2047
            int which = j >> 10;           // 0:A 1:B
            int idx   = j & 1023;
            int r     = idx >> 3;          // 0..127
            int ch    = idx & 7;           // 16B chunk (8 halves)
            uint32_t dst = s + (uint32_t)which * 16384u
                         + (uint32_t)r * 128u + ((uint32_t)(ch ^ (r & 7)) << 4);
            const __half* src = which ? &Bw[(size_t)(n0 + r) * Ee + k0 + ch * 8]
                                      : &A [(size_t)(m0 + r) * Ee + k0 + ch * 8];
            cpa16(dst, src);
        }
        cpa_commit();
    };

    float acc[4][4][4];
#pragma unroll
    for (int i = 0; i < 4; i++)
#pragma unroll
        for (int j = 0; j < 4; j++)
#pragma unroll
            for (int k = 0; k < 4; k++) acc[i][j][k] = 0.f;

    load_stage(0); load_stage(1);

    const int rA = wr * 64 + (lane & 15);
    const int cAadd = lane >> 4;
    const int rB = wc * 32 + (lane & 7) + ((lane >> 4) << 3);
    const int cBadd = (lane >> 3) & 1;

    for (int kb = 0; kb < 16; ++kb) {
        if (kb + 2 < 16) cpa_wait<1>(); else cpa_wait<0>();
        __syncthreads();
        if (kb + 2 < 16) load_stage(kb + 2);

        uint32_t As = stg + (uint32_t)(kb % 3) * 32768u;
        uint32_t Bs = As + 16384u;
#pragma unroll
        for (int ks = 0; ks < 4; ++ks) {            // 4 x k16
            uint32_t a[4][4];
#pragma unroll
            for (int mi = 0; mi < 4; mi++) {
                int row = rA + mi * 16;
                int ch  = 2 * ks + cAadd;
                uint32_t addr = As + (uint32_t)row * 128u
                              + ((uint32_t)(ch ^ (row & 7)) << 4);
                ldsm4(a[mi][0], a[mi][1], a[mi][2], a[mi][3], addr);
            }
            uint32_t b[2][4];
#pragma unroll
            for (int njp = 0; njp < 2; njp++) {
                int row = rB + njp * 16;
                int ch  = 2 * ks + cBadd;
                uint32_t addr = Bs + (uint32_t)row * 128u
                              + ((uint32_t)(ch ^ (row & 7)) << 4);
                ldsm4(b[njp][0], b[njp][1], b[njp][2], b[njp][3], addr);
            }
#pragma unroll
            for (int mi = 0; mi < 4; mi++)
#pragma unroll
                for (int nj = 0; nj < 4; nj++)
                    mma16(acc[mi][nj], a[mi],
                          b[nj >> 1][(nj & 1) * 2], b[nj >> 1][(nj & 1) * 2 + 1]);
        }
    }

#pragma unroll
    for (int mi = 0; mi < 4; mi++) {
        int r0 = m0 + wr * 64 + mi * 16 + (lane >> 2);
#pragma unroll
        for (int nj = 0; nj < 4; nj++) {
            int c0 = n0 + wc * 32 + nj * 8 + 2 * (lane & 3);
            if (HALF_OUT) {
                *(__half2*)&Ch[(size_t)r0 * Ee + c0] =
                    __floats2half2_rn(acc[mi][nj][0], acc[mi][nj][1]);
                *(__half2*)&Ch[(size_t)(r0 + 8) * Ee + c0] =
                    __floats2half2_rn(acc[mi][nj][2], acc[mi][nj][3]);
            } else {
                float2 v0 = {acc[mi][nj][0], acc[mi][nj][1]};
                float2 v1 = {acc[mi][nj][2], acc[mi][nj][3]};
                if (RES) {
                    float2 a0 = *(const float2*)&Resid[(size_t)r0 * Ee + c0];
                    float2 a1 = *(const float2*)&Resid[(size_t)(r0 + 8) * Ee + c0];
                    v0.x += a0.x; v0.y += a0.y; v1.x += a1.x; v1.y += a1.y;
                }
                *(float2*)&Cf[(size_t)r0 * Ee + c0]       = v0;
                *(float2*)&Cf[(size_t)(r0 + 8) * Ee + c0] = v1;
            }
        }
    }
}

// per-batch qkv: grid (8, 16, 3); m rows of batch bsel only
__global__ void __launch_bounds__(256, 2)
tc_qkv(int bsel)
{
    extern __shared__ char dsm[];
    int z = blockIdx.z;
    const __half* W = (z == 0) ? g_wqh : (z == 1) ? g_wkh : g_wvh;
    int m0 = bsel * Ss + blockIdx.y * 128;
    if (z == 2)
        gemm_core<false, false>(g_xh, W, nullptr, g_v, nullptr,
                                m0, blockIdx.x * 128, dsm);
    else
        gemm_core<true, false>(g_xh, W, (z == 0) ? g_qh : g_kh, nullptr, nullptr,
                               m0, blockIdx.x * 128, dsm);
}

// per-batch out: grid (8, 16)
__global__ void __launch_bounds__(256, 2)
tc_out(float* __restrict__ Out, int bsel)
{
    extern __shared__ char dsm[];
    gemm_core<false, true>(g_avh, g_woh, nullptr, Out, g_v,
                           bsel * Ss + blockIdx.y * 128, blockIdx.x * 128, dsm);
}

// ---------------------------------------------------------------------------
// Score pass (fp16 q,k), per batch: grid (16 qtiles LPT, 16 heads).
// S = Q[128x64] @ K[128x64]^T per causal k-tile, exp + row sums in regs,
// fused epilogue writes g_avh = (diag/rowsum) * v for this head slice.
// 256 threads, 8 warps (2x4), warp tile 64x32. SMEM: Q 16KB + 3 K x 16KB.
// ---------------------------------------------------------------------------
__global__ void __launch_bounds__(256, 2)
tc_score(int bsel)
{
    extern __shared__ char dsm[];
    const uint32_t Qs = smem_u32(dsm);
    const uint32_t Ks = Qs + 16384u;
    float* sSum  = (float*)(dsm + 16384 + 3 * 16384);
    float* sDiag = sSum + 128;

    const int qt = (int)(gridDim.x - 1 - blockIdx.x);   // LPT: heavy first
    const int h = blockIdx.y, b = bsel;
    const int tid = threadIdx.x;
    const int wid = tid >> 5, lane = tid & 31;
    const int wr = wid >> 2, wc = wid & 3;

    auto load_q = [&]() {
#pragma unroll
        for (int i = 0; i < 4; i++) {
            int j  = tid + i * 256;     // 0..1023
            int r  = j >> 3;            // 0..127
            int ch = j & 7;             // 8 chunks (64 halves/row)
            uint32_t dst = Qs + (uint32_t)r * 128u + ((uint32_t)(ch ^ (r & 7)) << 4);
            cpa16(dst, &g_qh[(size_t)(b * Ss + qt * 128 + r) * Ee + h * Dd + ch * 8]);
        }
    };
    auto load_k = [&](int kt, int slot) {
        uint32_t s = Ks + (uint32_t)slot * 16384u;
#pragma unroll
        for (int i = 0; i < 4; i++) {
            int j  = tid + i * 256;
            int r  = j >> 3;
            int ch = j & 7;
            uint32_t dst = s + (uint32_t)r * 128u + ((uint32_t)(ch ^ (r & 7)) << 4);
            cpa16(dst, &g_kh[(size_t)(b * Ss + kt * 128 + r) * Ee + h * Dd + ch * 8]);
        }
    };

    load_q(); load_k(0, 0); cpa_commit();
    if (qt >= 1) { load_k(1, 1); cpa_commit(); }

    if (tid < 128) { sSum[tid] = 0.f; sDiag[tid] = 0.f; }

    float rs[8], dv[8];
#pragma unroll
    for (int k = 0; k < 8; k++) { rs[k] = 0.f; dv[k] = 0.f; }

    const int rA = wr * 64 + (lane & 15);
    const int cAadd = lane >> 4;
    const int rB = wc * 32 + (lane & 7) + ((lane >> 4) << 3);
    const int cBadd = (lane >> 3) & 1;

    for (int kt = 0; kt <= qt; ++kt) {
        if (kt == qt) cpa_wait<0>(); else cpa_wait<1>();
        __syncthreads();
        if (kt + 2 <= qt) { load_k(kt + 2, (kt + 2) % 3); cpa_commit(); }

        float acc[4][4][4];
#pragma unroll
        for (int i = 0; i < 4; i++)
#pragma unroll
            for (int j = 0; j < 4; j++)
#pragma unroll
                for (int k = 0; k < 4; k++) acc[i][j][k] = 0.f;

        uint32_t Ksl = Ks + (uint32_t)(kt % 3) * 16384u;
#pragma unroll
        for (int ks = 0; ks < 4; ++ks) {
            uint32_t a[4][4];
#pragma unroll
            for (int mi = 0; mi < 4; mi++) {
                int row = rA + mi * 16;
                int ch  = 2 * ks + cAadd;
                uint32_t addr = Qs + (uint32_t)row * 128u
                              + ((uint32_t)(ch ^ (row & 7)) << 4);
                ldsm4(a[mi][0], a[mi][1], a[mi][2], a[mi][3], addr);
            }
            uint32_t bfr[2][4];
#pragma unroll
            for (int njp = 0; njp < 2; njp++) {
                int row = rB + njp * 16;
                int ch  = 2 * ks + cBadd;
                uint32_t addr = Ksl + (uint32_t)row * 128u
                              + ((uint32_t)(ch ^ (row & 7)) << 4);
                ldsm4(bfr[njp][0], bfr[njp][1], bfr[njp][2], bfr[njp][3], addr);
            }
#pragma unroll
            for (int mi = 0; mi < 4; mi++)
#pragma unroll
                for (int nj = 0; nj < 4; nj++)
                    mma16(acc[mi][nj], a[mi],
                          bfr[nj >> 1][(nj & 1) * 2], bfr[nj >> 1][(nj & 1) * 2 + 1]);
        }

        const bool dt = (kt == qt);
#pragma unroll
        for (int mi = 0; mi < 4; mi++) {
            int il0 = wr * 64 + mi * 16 + (lane >> 2);
#pragma unroll
            for (int nj = 0; nj < 4; nj++) {
                int jl = wc * 32 + nj * 8 + 2 * (lane & 3);
#pragma unroll
                for (int q = 0; q < 4; q++) {
                    int il = il0 + (q >> 1) * 8;
                    int j  = jl  + (q & 1);
                    float e = fast_exp(acc[mi][nj][q] * 0.03125f);
                    if (dt) {
                        if (j > il)  e = 0.f;
                        if (j == il) dv[mi * 2 + (q >> 1)] = e;
                    }
                    rs[mi * 2 + (q >> 1)] += e;
                }
            }
        }
    }

    // quad reduce (lanes in a quad share rows), then cross-warp via smem atomics
#pragma unroll
    for (int k = 0; k < 8; k++) {
        rs[k] += __shfl_xor_sync(0xffffffffu, rs[k], 1);
        rs[k] += __shfl_xor_sync(0xffffffffu, rs[k], 2);
        dv[k] += __shfl_xor_sync(0xffffffffu, dv[k], 1);
        dv[k] += __shfl_xor_sync(0xffffffffu, dv[k], 2);
    }
    if ((lane & 3) == 0) {
#pragma unroll
        for (int k = 0; k < 8; k++) {
            int row = wr * 64 + (k >> 1) * 16 + (k & 1) * 8 + (lane >> 2);
            atomicAdd(&sSum[row], rs[k]);
            atomicAdd(&sDiag[row], dv[k]);
        }
    }
    __syncthreads();

    // fused gv epilogue: g_avh[row, head slice] = (diag/rowsum) * v
    // vectorized: 4 x 16B stores per thread (offsets are 64-half aligned)
    {
        int r  = tid >> 1;                   // 0..127
        int c0 = (tid & 1) * 32;             // half of the 64-wide head slice
        float gv = sDiag[r] / sSum[r];
        size_t rowg = (size_t)(b * Ss + qt * 128 + r) * Ee + h * Dd + c0;
#pragma unroll
        for (int c = 0; c < 32; c += 8) {
            float4 v0 = *(const float4*)&g_v[rowg + c];
            float4 v1 = *(const float4*)&g_v[rowg + c + 4];
            uint4 st;
            st.x = pack_h2(v0.x * gv, v0.y * gv);
            st.y = pack_h2(v0.z * gv, v0.w * gv);
            st.z = pack_h2(v1.x * gv, v1.y * gv);
            st.w = pack_h2(v1.z * gv, v1.w * gv);
            *(uint4*)&g_avh[rowg + c] = st;
        }
    }
}

// ---------------------------------------------------------------------------
extern "C" void kernel_launch(void* const* d_in, const int* in_sizes, int n_in,
                              void* d_out, int out_size)
{
    const float* x  = (const float*)d_in[0];
    const float* wq = (const float*)d_in[1];
    const float* wk = (const float*)d_in[2];
    const float* wv = (const float*)d_in[3];
    const float* wo = (const float*)d_in[4];
    float* out = (float*)d_out;

    const int SMEM_GEMM  = 3 * 32768;                 // 96 KB
    const int SMEM_SCORE = 16384 + 3 * 16384 + 1024;  // 64 KB + reduce

    cudaFuncSetAttribute(tc_qkv,   cudaFuncAttributeMaxDynamicSharedMemorySize, SMEM_GEMM);
    cudaFuncSetAttribute(tc_out,   cudaFuncAttributeMaxDynamicSharedMemorySize, SMEM_GEMM);
    cudaFuncSetAttribute(tc_score, cudaFuncAttributeMaxDynamicSharedMemorySize, SMEM_SCORE);

    // Two streams (guard-proven budget: 1 created stream + 4 events).
    cudaStream_t sB;
    cudaStreamCreateWithFlags(&sB, cudaStreamNonBlocking);
    cudaEvent_t evF, evX, evW, evB;
    cudaEventCreateWithFlags(&evF, cudaEventDisableTiming);
    cudaEventCreateWithFlags(&evX, cudaEventDisableTiming);
    cudaEventCreateWithFlags(&evW, cudaEventDisableTiming);
    cudaEventCreateWithFlags(&evB, cudaEventDisableTiming);

    cudaEventRecord(evF, 0);
    cudaStreamWaitEvent(sB, evF, 0);

    // parallel conversions: x on s0, weights on sB
    cvt_x<<<(unsigned)((long)Mm * Ee / 4 / 256), 256, 0, 0>>>(x);
    cudaEventRecord(evX, 0);
    cvt_w<<<(unsigned)(4L * Ee * Ee / 4 / 256), 256, 0, sB>>>(wq, wk, wv, wo);
    cudaEventRecord(evW, sB);

    // each chain needs both conversions
    cudaStreamWaitEvent(0, evW, 0);
    cudaStreamWaitEvent(sB, evX, 0);

    // chain A (batch 0) on the default stream
    tc_qkv  <<<dim3(8, 16, 3), 256, SMEM_GEMM,  0>>>(0);
    tc_score<<<dim3(16, 16),   256, SMEM_SCORE, 0>>>(0);
    tc_out  <<<dim3(8, 16),    256, SMEM_GEMM,  0>>>(out, 0);

    // chain B (batch 1) on sB
    tc_qkv  <<<dim3(8, 16, 3), 256, SMEM_GEMM,  sB>>>(1);
    tc_score<<<dim3(16, 16),   256, SMEM_SCORE, sB>>>(1);
    tc_out  <<<dim3(8, 16),    256, SMEM_GEMM,  sB>>>(out, 1);

    cudaEventRecord(evB, sB);
    cudaStreamWaitEvent(0, evB, 0);
}

// round 17
// speedup vs baseline: 1.7288x; 1.7055x over previous
#include <cuda_runtime.h>
#include <cuda_fp16.h>
#include <cstdint>
#include <cstddef>

#define Bb 2
#define Ss 2048
#define Ee 1024
#define Hh 16
#define Dd 64
#define Mm (Bb*Ss)

// ---------------------------------------------------------------------------
// Scratch (fp16 operand chain + fp32 v for residual)
// ---------------------------------------------------------------------------
__device__ __half g_xh [Mm * Ee];     // x in fp16
__device__ __half g_wqh[Ee * Ee];
__device__ __half g_wkh[Ee * Ee];
__device__ __half g_wvh[Ee * Ee];
__device__ __half g_woh[Ee * Ee];
__device__ __half g_qh [Mm * Ee];     // q (fp16)
__device__ __half g_kh [Mm * Ee];     // k (fp16)
__device__ __half g_avh[Mm * Ee];     // g ⊙ v (fp16)
__device__ float  g_v  [Mm * Ee];     // v (fp32, residual)

// ---------------------------------------------------------------------------
// Helpers (family-agnostic PTX: cp.async, ldmatrix, mma.sync — sm_80+)
// ---------------------------------------------------------------------------
__device__ __forceinline__ uint32_t smem_u32(const void* p) {
    uint32_t a;
    asm("{ .reg .u64 t; cvta.to.shared.u64 t, %1; cvt.u32.u64 %0, t; }"
        : "=r"(a) : "l"(p));
    return a;
}
__device__ __forceinline__ void cpa16(uint32_t s, const void* g) {
    asm volatile("cp.async.cg.shared.global [%0], [%1], 16;" :: "r"(s), "l"(g));
}
__device__ __forceinline__ void cpa_commit() {
    asm volatile("cp.async.commit_group;" ::: "memory");
}
template<int N> __device__ __forceinline__ void cpa_wait() {
    asm volatile("cp.async.wait_group %0;" :: "n"(N) : "memory");
}
__device__ __forceinline__ void ldsm4(uint32_t& r0, uint32_t& r1,
                                      uint32_t& r2, uint32_t& r3, uint32_t addr) {
    asm volatile("ldmatrix.sync.aligned.m8n8.x4.shared.b16 {%0,%1,%2,%3}, [%4];"
                 : "=r"(r0), "=r"(r1), "=r"(r2), "=r"(r3) : "r"(addr));
}
// f16 mma, fp32 accumulate
__device__ __forceinline__ void mma16(float* c, const uint32_t* a,
                                      uint32_t b0, uint32_t b1) {
    asm volatile(
        "mma.sync.aligned.m16n8k16.row.col.f32.f16.f16.f32 "
        "{%0,%1,%2,%3}, {%4,%5,%6,%7}, {%8,%9}, {%0,%1,%2,%3};"
        : "+f"(c[0]), "+f"(c[1]), "+f"(c[2]), "+f"(c[3])
        : "r"(a[0]), "r"(a[1]), "r"(a[2]), "r"(a[3]), "r"(b0), "r"(b1));
}

// MUFU exp: e = 2^(x * log2(e)/32) == exp(x/32). One FFMA-mul + one MUFU.
#define EXP_SCALE 0.045084220027780106f   // log2(e) / 32
__device__ __forceinline__ float exp2_approx(float x) {
    float y;
    asm("ex2.approx.ftz.f32 %0, %1;" : "=f"(y) : "f"(x));
    return y;
}

__device__ __forceinline__ uint32_t pack_h2(float a, float b) {
    __half2 h = __floats2half2_rn(a, b);
    return *(uint32_t*)&h;
}

// ---------------------------------------------------------------------------
// fp32 -> fp16 (RN) pre-passes: x on one stream, weights on the other
// ---------------------------------------------------------------------------
__global__ void __launch_bounds__(256) cvt_x(const float* __restrict__ x)
{
    long i = ((long)blockIdx.x * 256 + threadIdx.x) * 4;
    float4 v = *(const float4*)&x[i];
    *(__half2*)&g_xh[i]     = __floats2half2_rn(v.x, v.y);
    *(__half2*)&g_xh[i + 2] = __floats2half2_rn(v.z, v.w);
}

__global__ void __launch_bounds__(256) cvt_w(const float* __restrict__ wq,
                                             const float* __restrict__ wk,
                                             const float* __restrict__ wv,
                                             const float* __restrict__ wo)
{
    long j = ((long)blockIdx.x * 256 + threadIdx.x) * 4;
    int  w = (int)(j >> 20);                 // Ee*Ee = 1<<20
    long off = j & ((1L << 20) - 1);
    const float* src = (w == 0) ? wq : (w == 1) ? wk : (w == 2) ? wv : wo;
    __half* dst = (w == 0) ? g_wqh : (w == 1) ? g_wkh : (w == 2) ? g_wvh : g_woh;
    float4 v = *(const float4*)&src[off];
    *(__half2*)&dst[off]     = __floats2half2_rn(v.x, v.y);
    *(__half2*)&dst[off + 2] = __floats2half2_rn(v.z, v.w);
}

// ---------------------------------------------------------------------------
// fp16 GEMM core: C[128x128] = A[128xK] @ Bw[128xK]^T (+Resid)
// 256 threads (8 warps, 2x4). Warp tile 64x32. BK=64 halves, 3-stage cp.async.
// ---------------------------------------------------------------------------
template<bool HALF_OUT, bool RES>
__device__ __forceinline__ void gemm_core(const __half* __restrict__ A,
                                          const __half* __restrict__ Bw,
                                          __half* __restrict__ Ch,
                                          float* __restrict__ Cf,
                                          const float* __restrict__ Resid,
                                          int m0, int n0, char* dsm)
{
    const uint32_t stg = smem_u32(dsm);
    const int tid = threadIdx.x;
    const int wid = tid >> 5, lane = tid & 31;
    const int wr = wid >> 2, wc = wid & 3;

    auto load_stage = [&](int kb) {
        uint32_t s = stg + (uint32_t)(kb % 3) * 32768u;
        int k0 = kb * 64;                  // in halves
#pragma unroll
        for (int i = 0; i < 8; i++) {
            int j     = tid + i * 256;     // 0..2047
            int which = j >> 10;           // 0:A 1:B
            int idx   = j & 1023;
            int r     = idx >> 3;          // 0..127
            int ch    = idx & 7;           // 16B chunk (8 halves)
            uint32_t dst = s + (uint32_t)which * 16384u
                         + (uint32_t)r * 128u + ((uint32_t)(ch ^ (r & 7)) << 4);
            const __half* src = which ? &Bw[(size_t)(n0 + r) * Ee + k0 + ch * 8]
                                      : &A [(size_t)(m0 + r) * Ee + k0 + ch * 8];
            cpa16(dst, src);
        }
        cpa_commit();
    };

    float acc[4][4][4];
#pragma unroll
    for (int i = 0; i < 4; i++)
#pragma unroll
        for (int j = 0; j < 4; j++)
#pragma unroll
            for (int k = 0; k < 4; k++) acc[i][j][k] = 0.f;

    load_stage(0); load_stage(1);

    const int rA = wr * 64 + (lane & 15);
    const int cAadd = lane >> 4;
    const int rB = wc * 32 + (lane & 7) + ((lane >> 4) << 3);
    const int cBadd = (lane >> 3) & 1;

    for (int kb = 0; kb < 16; ++kb) {
        if (kb + 2 < 16) cpa_wait<1>(); else cpa_wait<0>();
        __syncthreads();
        if (kb + 2 < 16) load_stage(kb + 2);

        uint32_t As = stg + (uint32_t)(kb % 3) * 32768u;
        uint32_t Bs = As + 16384u;
#pragma unroll
        for (int ks = 0; ks < 4; ++ks) {            // 4 x k16
            uint32_t a[4][4];
#pragma unroll
            for (int mi = 0; mi < 4; mi++) {
                int row = rA + mi * 16;
                int ch  = 2 * ks + cAadd;
                uint32_t addr = As + (uint32_t)row * 128u
                              + ((uint32_t)(ch ^ (row & 7)) << 4);
                ldsm4(a[mi][0], a[mi][1], a[mi][2], a[mi][3], addr);
            }
            uint32_t b[2][4];
#pragma unroll
            for (int njp = 0; njp < 2; njp++) {
                int row = rB + njp * 16;
                int ch  = 2 * ks + cBadd;
                uint32_t addr = Bs + (uint32_t)row * 128u
                              + ((uint32_t)(ch ^ (row & 7)) << 4);
                ldsm4(b[njp][0], b[njp][1], b[njp][2], b[njp][3], addr);
            }
#pragma unroll
            for (int mi = 0; mi < 4; mi++)
#pragma unroll
                for (int nj = 0; nj < 4; nj++)
                    mma16(acc[mi][nj], a[mi],
                          b[nj >> 1][(nj & 1) * 2], b[nj >> 1][(nj & 1) * 2 + 1]);
        }
    }

#pragma unroll
    for (int mi = 0; mi < 4; mi++) {
        int r0 = m0 + wr * 64 + mi * 16 + (lane >> 2);
#pragma unroll
        for (int nj = 0; nj < 4; nj++) {
            int c0 = n0 + wc * 32 + nj * 8 + 2 * (lane & 3);
            if (HALF_OUT) {
                *(__half2*)&Ch[(size_t)r0 * Ee + c0] =
                    __floats2half2_rn(acc[mi][nj][0], acc[mi][nj][1]);
                *(__half2*)&Ch[(size_t)(r0 + 8) * Ee + c0] =
                    __floats2half2_rn(acc[mi][nj][2], acc[mi][nj][3]);
            } else {
                float2 v0 = {acc[mi][nj][0], acc[mi][nj][1]};
                float2 v1 = {acc[mi][nj][2], acc[mi][nj][3]};
                if (RES) {
                    float2 a0 = *(const float2*)&Resid[(size_t)r0 * Ee + c0];
                    float2 a1 = *(const float2*)&Resid[(size_t)(r0 + 8) * Ee + c0];
                    v0.x += a0.x; v0.y += a0.y; v1.x += a1.x; v1.y += a1.y;
                }
                *(float2*)&Cf[(size_t)r0 * Ee + c0]       = v0;
                *(float2*)&Cf[(size_t)(r0 + 8) * Ee + c0] = v1;
            }
        }
    }
}

// per-batch qkv: grid (8, 16, 3); m rows of batch bsel only
__global__ void __launch_bounds__(256, 2)
tc_qkv(int bsel)
{
    extern __shared__ char dsm[];
    int z = blockIdx.z;
    const __half* W = (z == 0) ? g_wqh : (z == 1) ? g_wkh : g_wvh;
    int m0 = bsel * Ss + blockIdx.y * 128;
    if (z == 2)
        gemm_core<false, false>(g_xh, W, nullptr, g_v, nullptr,
                                m0, blockIdx.x * 128, dsm);
    else
        gemm_core<true, false>(g_xh, W, (z == 0) ? g_qh : g_kh, nullptr, nullptr,
                               m0, blockIdx.x * 128, dsm);
}

// per-batch out: grid (8, 16)
__global__ void __launch_bounds__(256, 2)
tc_out(float* __restrict__ Out, int bsel)
{
    extern __shared__ char dsm[];
    gemm_core<false, true>(g_avh, g_woh, nullptr, Out, g_v,
                           bsel * Ss + blockIdx.y * 128, blockIdx.x * 128, dsm);
}

// ---------------------------------------------------------------------------
// Score pass (fp16 q,k), per batch: grid (16 qtiles LPT, 16 heads).
// S = Q[128x64] @ K[128x64]^T per causal k-tile; softmax epilogue uses a
// single MUFU ex2 per element (e = 2^(score * log2e/32) == exp(score/32)).
// Fused epilogue writes g_avh = (diag/rowsum) * v for this head slice.
// ---------------------------------------------------------------------------
__global__ void __launch_bounds__(256, 2)
tc_score(int bsel)
{
    extern __shared__ char dsm[];
    const uint32_t Qs = smem_u32(dsm);
    const uint32_t Ks = Qs + 16384u;
    float* sSum  = (float*)(dsm + 16384 + 3 * 16384);
    float* sDiag = sSum + 128;

    const int qt = (int)(gridDim.x - 1 - blockIdx.x);   // LPT: heavy first
    const int h = blockIdx.y, b = bsel;
    const int tid = threadIdx.x;
    const int wid = tid >> 5, lane = tid & 31;
    const int wr = wid >> 2, wc = wid & 3;

    auto load_q = [&]() {
#pragma unroll
        for (int i = 0; i < 4; i++) {
            int j  = tid + i * 256;     // 0..1023
            int r  = j >> 3;            // 0..127
            int ch = j & 7;             // 8 chunks (64 halves/row)
            uint32_t dst = Qs + (uint32_t)r * 128u + ((uint32_t)(ch ^ (r & 7)) << 4);
            cpa16(dst, &g_qh[(size_t)(b * Ss + qt * 128 + r) * Ee + h * Dd + ch * 8]);
        }
    };
    auto load_k = [&](int kt, int slot) {
        uint32_t s = Ks + (uint32_t)slot * 16384u;
#pragma unroll
        for (int i = 0; i < 4; i++) {
            int j  = tid + i * 256;
            int r  = j >> 3;
            int ch = j & 7;
            uint32_t dst = s + (uint32_t)r * 128u + ((uint32_t)(ch ^ (r & 7)) << 4);
            cpa16(dst, &g_kh[(size_t)(b * Ss + kt * 128 + r) * Ee + h * Dd + ch * 8]);
        }
    };

    load_q(); load_k(0, 0); cpa_commit();
    if (qt >= 1) { load_k(1, 1); cpa_commit(); }

    if (tid < 128) { sSum[tid] = 0.f; sDiag[tid] = 0.f; }

    float rs[8], dv[8];
#pragma unroll
    for (int k = 0; k < 8; k++) { rs[k] = 0.f; dv[k] = 0.f; }

    const int rA = wr * 64 + (lane & 15);
    const int cAadd = lane >> 4;
    const int rB = wc * 32 + (lane & 7) + ((lane >> 4) << 3);
    const int cBadd = (lane >> 3) & 1;

    for (int kt = 0; kt <= qt; ++kt) {
        if (kt == qt) cpa_wait<0>(); else cpa_wait<1>();
        __syncthreads();
        if (kt + 2 <= qt) { load_k(kt + 2, (kt + 2) % 3); cpa_commit(); }

        float acc[4][4][4];
#pragma unroll
        for (int i = 0; i < 4; i++)
#pragma unroll
            for (int j = 0; j < 4; j++)
#pragma unroll
                for (int k = 0; k < 4; k++) acc[i][j][k] = 0.f;

        uint32_t Ksl = Ks + (uint32_t)(kt % 3) * 16384u;
#pragma unroll
        for (int ks = 0; ks < 4; ++ks) {
            uint32_t a[4][4];
#pragma unroll
            for (int mi = 0; mi < 4; mi++) {
                int row = rA + mi * 16;
                int ch  = 2 * ks + cAadd;
                uint32_t addr = Qs + (uint32_t)row * 128u
                              + ((uint32_t)(ch ^ (row & 7)) << 4);
                ldsm4(a[mi][0], a[mi][1], a[mi][2], a[mi][3], addr);
            }
            uint32_t bfr[2][4];
#pragma unroll
            for (int njp = 0; njp < 2; njp++) {
                int row = rB + njp * 16;
                int ch  = 2 * ks + cBadd;
                uint32_t addr = Ksl + (uint32_t)row * 128u
                              + ((uint32_t)(ch ^ (row & 7)) << 4);
                ldsm4(bfr[njp][0], bfr[njp][1], bfr[njp][2], bfr[njp][3], addr);
            }
#pragma unroll
            for (int mi = 0; mi < 4; mi++)
#pragma unroll
                for (int nj = 0; nj < 4; nj++)
                    mma16(acc[mi][nj], a[mi],
                          bfr[nj >> 1][(nj & 1) * 2], bfr[nj >> 1][(nj & 1) * 2 + 1]);
        }

        const bool dt = (kt == qt);
#pragma unroll
        for (int mi = 0; mi < 4; mi++) {
            int il0 = wr * 64 + mi * 16 + (lane >> 2);
#pragma unroll
            for (int nj = 0; nj < 4; nj++) {
                int jl = wc * 32 + nj * 8 + 2 * (lane & 3);
#pragma unroll
                for (int q = 0; q < 4; q++) {
                    int il = il0 + (q >> 1) * 8;
                    int j  = jl  + (q & 1);
                    // e = exp(score/32) via single MUFU ex2
                    float e = exp2_approx(acc[mi][nj][q] * EXP_SCALE);
                    if (dt) {
                        if (j > il)  e = 0.f;
                        if (j == il) dv[mi * 2 + (q >> 1)] = e;
                    }
                    rs[mi * 2 + (q >> 1)] += e;
                }
            }
        }
    }

    // quad reduce (lanes in a quad share rows), then cross-warp via smem atomics
#pragma unroll
    for (int k = 0; k < 8; k++) {
        rs[k] += __shfl_xor_sync(0xffffffffu, rs[k], 1);
        rs[k] += __shfl_xor_sync(0xffffffffu, rs[k], 2);
        dv[k] += __shfl_xor_sync(0xffffffffu, dv[k], 1);
        dv[k] += __shfl_xor_sync(0xffffffffu, dv[k], 2);
    }
    if ((lane & 3) == 0) {
#pragma unroll
        for (int k = 0; k < 8; k++) {
            int row = wr * 64 + (k >> 1) * 16 + (k & 1) * 8 + (lane >> 2);
            atomicAdd(&sSum[row], rs[k]);
            atomicAdd(&sDiag[row], dv[k]);
        }
    }
    __syncthreads();

    // fused gv epilogue: g_avh[row, head slice] = (diag/rowsum) * v
    // vectorized: 4 x 16B stores per thread (offsets are 64-half aligned)
    {
        int r  = tid >> 1;                   // 0..127
        int c0 = (tid & 1) * 32;             // half of the 64-wide head slice
        float gv = sDiag[r] / sSum[r];
        size_t rowg = (size_t)(b * Ss + qt * 128 + r) * Ee + h * Dd + c0;
#pragma unroll
        for (int c = 0; c < 32; c += 8) {
            float4 v0 = *(const float4*)&g_v[rowg + c];
            float4 v1 = *(const float4*)&g_v[rowg + c + 4];
            uint4 st;
            st.x = pack_h2(v0.x * gv, v0.y * gv);
            st.y = pack_h2(v0.z * gv, v0.w * gv);
            st.z = pack_h2(v1.x * gv, v1.y * gv);
            st.w = pack_h2(v1.z * gv, v1.w * gv);
            *(uint4*)&g_avh[rowg + c] = st;
        }
    }
}

// ---------------------------------------------------------------------------
extern "C" void kernel_launch(void* const* d_in, const int* in_sizes, int n_in,
                              void* d_out, int out_size)
{
    const float* x  = (const float*)d_in[0];
    const float* wq = (const float*)d_in[1];
    const float* wk = (const float*)d_in[2];
    const float* wv = (const float*)d_in[3];
    const float* wo = (const float*)d_in[4];
    float* out = (float*)d_out;

    const int SMEM_GEMM  = 3 * 32768;                 // 96 KB
    const int SMEM_SCORE = 16384 + 3 * 16384 + 1024;  // 64 KB + reduce

    cudaFuncSetAttribute(tc_qkv,   cudaFuncAttributeMaxDynamicSharedMemorySize, SMEM_GEMM);
    cudaFuncSetAttribute(tc_out,   cudaFuncAttributeMaxDynamicSharedMemorySize, SMEM_GEMM);
    cudaFuncSetAttribute(tc_score, cudaFuncAttributeMaxDynamicSharedMemorySize, SMEM_SCORE);

    // Two streams (guard-proven budget: 1 created stream + 4 events).
    cudaStream_t sB;
    cudaStreamCreateWithFlags(&sB, cudaStreamNonBlocking);
    cudaEvent_t evF, evX, evW, evB;
    cudaEventCreateWithFlags(&evF, cudaEventDisableTiming);
    cudaEventCreateWithFlags(&evX, cudaEventDisableTiming);
    cudaEventCreateWithFlags(&evW, cudaEventDisableTiming);
    cudaEventCreateWithFlags(&evB, cudaEventDisableTiming);

    cudaEventRecord(evF, 0);
    cudaStreamWaitEvent(sB, evF, 0);

    // parallel conversions: x on s0, weights on sB
    cvt_x<<<(unsigned)((long)Mm * Ee / 4 / 256), 256, 0, 0>>>(x);
    cudaEventRecord(evX, 0);
    cvt_w<<<(unsigned)(4L * Ee * Ee / 4 / 256), 256, 0, sB>>>(wq, wk, wv, wo);
    cudaEventRecord(evW, sB);

    // each chain needs both conversions
    cudaStreamWaitEvent(0, evW, 0);
    cudaStreamWaitEvent(sB, evX, 0);

    // chain A (batch 0) on the default stream
    tc_qkv  <<<dim3(8, 16, 3), 256, SMEM_GEMM,  0>>>(0);
    tc_score<<<dim3(16, 16),   256, SMEM_SCORE, 0>>>(0);
    tc_out  <<<dim3(8, 16),    256, SMEM_GEMM,  0>>>(out, 0);

    // chain B (batch 1) on sB
    tc_qkv  <<<dim3(8, 16, 3), 256, SMEM_GEMM,  sB>>>(1);
    tc_score<<<dim3(16, 16),   256, SMEM_SCORE, sB>>>(1);
    tc_out  <<<dim3(8, 16),    256, SMEM_GEMM,  sB>>>(out, 1);

    cudaEventRecord(evB, sB);
    cudaStreamWaitEvent(0, evB, 0);
}